// round 1
// baseline (speedup 1.0000x reference)
#include <cuda_runtime.h>

#define N_OUT   100000
#define KBINS   9
#define C_IN    32
#define C_A     24
#define C_B     8
#define C_OUT   32
#define JTOT    (KBINS * C_IN)      // 288
#define GROUPS  ((N_OUT + 7) / 8)   // 12500

// Scratch (device globals; no allocation allowed)
__device__ float g_Wt[JTOT][C_OUT];        // Wt[j][f] : j = k*32+c
__device__ int   g_row_start[N_OUT + 1];   // CSR offsets into edge list

// ---------------------------------------------------------------------------
// Prep 1: transpose/interleave weights into [j][f] layout (f coalesced)
// ---------------------------------------------------------------------------
__global__ void prep_wt_kernel(const float* __restrict__ W_a,
                               const float* __restrict__ W_b) {
    int idx = blockIdx.x * blockDim.x + threadIdx.x;
    if (idx >= JTOT * C_OUT) return;
    int j = idx / C_OUT, f = idx % C_OUT;
    int k = j / C_IN,  c = j % C_IN;
    float w = (f < C_A) ? W_a[(k * C_IN + c) * C_A + f]
                        : W_b[(k * C_IN + c) * C_B + (f - C_A)];
    g_Wt[j][f] = w;
}

// ---------------------------------------------------------------------------
// Prep 2: CSR row starts via binary search over sorted neighbors_out_index
// ---------------------------------------------------------------------------
__global__ void prep_rows_kernel(const int* __restrict__ out_idx, int E) {
    int n = blockIdx.x * blockDim.x + threadIdx.x;
    if (n > N_OUT) return;
    int lo = 0, hi = E;
    while (lo < hi) {
        int mid = (lo + hi) >> 1;
        if (out_idx[mid] < n) lo = mid + 1; else hi = mid;
    }
    g_row_start[n] = lo;
}

// ---------------------------------------------------------------------------
// Main fused kernel: 256 threads/block, 8 warps -> 8 outputs per group.
// Phase 1: warp-per-output CSR scatter-accumulate into registers.
// Phase 2: register-blocked epilogue GEMM (thread = (f, j-slice), 8 outputs).
// ---------------------------------------------------------------------------
__global__ __launch_bounds__(256)
void sparse_conv_main(const float* __restrict__ feats,
                      const float* __restrict__ importance,
                      const float* __restrict__ b_a,
                      const float* __restrict__ b_b,
                      const int*   __restrict__ nb_idx,
                      const int*   __restrict__ nb_k,
                      float*       __restrict__ out) {
    // Padded rows (9 floats): gcd(9,32)=1 -> conflict-free transpose stores.
    __shared__ float Ssm_a[JTOT][9];    // S_a[j][o]   (o = output-in-group)
    __shared__ float Ssm_b[JTOT][9];    // S_b[j][o]
    __shared__ float Psm[8][C_OUT][9];  // partials [o][f][slice]
    __shared__ float impsm[8];

    const int tid  = threadIdx.x;
    const int w    = tid >> 5;          // warp id == output-in-group == j-slice
    const int lane = tid & 31;          // channel c in phase 1, feature f in phase 2
    const int f    = lane;

    const float bias = (f < C_A) ? b_a[f] : b_b[f - C_A];

    for (int g = blockIdx.x; g < GROUPS; g += gridDim.x) {
        // ----------------- Phase 1: scatter-accumulate -----------------
        const int n = g * 8 + w;
        float Sa[KBINS], Sb[KBINS];
        #pragma unroll
        for (int q = 0; q < KBINS; q++) { Sa[q] = 0.f; Sb[q] = 0.f; }
        float isum = 0.f;

        if (n < N_OUT) {
            const int e0 = g_row_start[n];
            const int e1 = g_row_start[n + 1];
            for (int base = e0; base < e1; base += 32) {
                const int e = base + lane;
                int ni = 0, kk = 0;
                float ii = 0.f;
                if (e < e1) {
                    ni = nb_idx[e];
                    kk = nb_k[e];
                    ii = importance[ni];
                }
                const int cnt = min(32, e1 - base);
                for (int j = 0; j < cnt; j++) {
                    const int   nij = __shfl_sync(0xffffffffu, ni, j);
                    const int   kj  = __shfl_sync(0xffffffffu, kk, j);
                    const float ij  = __shfl_sync(0xffffffffu, ii, j);
                    const float v   = feats[nij * C_IN + lane];  // 128B coalesced, L2-hot
                    isum += ij;
                    #pragma unroll
                    for (int q = 0; q < KBINS; q++) {
                        if (kj == q) {
                            Sa[q] += v;
                            Sb[q] = fmaf(v, ij, Sb[q]);
                        }
                    }
                }
            }
        }

        // Stage S into smem transposed: row j = q*32+lane, column = output w
        #pragma unroll
        for (int q = 0; q < KBINS; q++) {
            Ssm_a[q * 32 + lane][w] = Sa[q];
            Ssm_b[q * 32 + lane][w] = Sb[q];
        }
        if (lane == 0) impsm[w] = isum;
        __syncthreads();

        // ----------------- Phase 2: epilogue GEMM -----------------
        // thread (f = lane, slice = w) handles 36 j's for all 8 outputs.
        float acc[8];
        #pragma unroll
        for (int o = 0; o < 8; o++) acc[o] = 0.f;

        const float* sbase = (f < C_A) ? &Ssm_a[0][0] : &Ssm_b[0][0];
        const int jbase = w * (JTOT / 8);   // 36 per slice
        #pragma unroll
        for (int jj = 0; jj < JTOT / 8; jj++) {
            const int j = jbase + jj;
            const float wv = g_Wt[j][f];           // coalesced, L1-resident (36.9KB)
            const float* srow = sbase + j * 9;     // broadcast across warp
            #pragma unroll
            for (int o = 0; o < 8; o++)
                acc[o] = fmaf(srow[o], wv, acc[o]);
        }
        #pragma unroll
        for (int o = 0; o < 8; o++)
            Psm[o][f][w] = acc[o];
        __syncthreads();

        // Final reduce: thread (o = w, f) sums 8 slice-partials, applies
        // normalization + bias + relu, writes output.
        {
            const int o  = w;
            const int n2 = g * 8 + o;
            if (n2 < N_OUT) {
                float s = 0.f;
                #pragma unroll
                for (int sl = 0; sl < 8; sl++) s += Psm[o][f][sl];
                const float iv    = impsm[o];
                const float denom = (iv > 0.f) ? iv : 1.f;
                float r = (f < C_A) ? (s + bias) : (s / denom + bias);
                r = fmaxf(r, 0.f);
                out[n2 * C_OUT + f] = r;
                if (f == 0) out[N_OUT * C_OUT + n2] = iv;   // out_imp
            }
        }
        __syncthreads();   // protect smem before next group's phase 1
    }
}

// ---------------------------------------------------------------------------
extern "C" void kernel_launch(void* const* d_in, const int* in_sizes, int n_in,
                              void* d_out, int out_size) {
    const float* feats      = (const float*)d_in[0];
    const float* importance = (const float*)d_in[1];
    const float* W_a        = (const float*)d_in[2];
    const float* b_a        = (const float*)d_in[3];
    const float* W_b        = (const float*)d_in[4];
    const float* b_b        = (const float*)d_in[5];
    const int*   nb_idx     = (const int*)d_in[6];
    const int*   nb_k       = (const int*)d_in[7];
    const int*   nb_out     = (const int*)d_in[8];
    const int E = in_sizes[6];

    prep_wt_kernel<<<(JTOT * C_OUT + 255) / 256, 256>>>(W_a, W_b);
    prep_rows_kernel<<<(N_OUT + 1 + 255) / 256, 256>>>(nb_out, E);
    sparse_conv_main<<<1480, 256>>>(feats, importance, b_a, b_b,
                                    nb_idx, nb_k, (float*)d_out);
}